// round 16
// baseline (speedup 1.0000x reference)
#include <cuda_runtime.h>
#include <math.h>
#include <stdint.h>

#define B 512
#define S 512
#define WW 3
#define E 128
#define H 100
#define T 64

// Scratch (static device globals — no runtime allocation)
__device__ float g_em[(size_t)S * B * T];   // em[s][b][t]
__device__ float g_mask[(size_t)S * B];

typedef unsigned long long u64;

#define KP1 64      // k-pairs for GEMM1 (E/2)
#define JP  104     // H padded to 8
#define KP2 50      // k-pairs for GEMM2 (H/2)

__device__ __align__(16) u64 gW1p[KP1 * JP];   // (W1[2kp][j], W1[2kp+1][j])
__device__ __align__(16) u64 gW2p[KP2 * T];    // (W2[2kp][t], W2[2kp+1][t])

// ---- helpers ---------------------------------------------------------------
__device__ __forceinline__ u64 pack2(float lo, float hi) {
    u64 d; asm("mov.b64 %0, {%1, %2};" : "=l"(d) : "f"(lo), "f"(hi)); return d;
}
__device__ __forceinline__ void unpack2(float& lo, float& hi, u64 v) {
    asm("mov.b64 {%0, %1}, %2;" : "=f"(lo), "=f"(hi) : "l"(v));
}
__device__ __forceinline__ u64 fma2(u64 a, u64 b2, u64 c) {
    u64 d; asm("fma.rn.f32x2 %0, %1, %2, %3;" : "=l"(d) : "l"(a), "l"(b2), "l"(c));
    return d;
}
__device__ __forceinline__ float ex2f(float x) {
    float r; asm("ex2.approx.f32 %0, %1;" : "=f"(r) : "f"(x)); return r;
}
__device__ __forceinline__ float exp_f(float x) { return ex2f(x * 1.4426950408889634f); }
__device__ __forceinline__ float log_f(float x) {
    float r; asm("lg2.approx.f32 %0, %1;" : "=f"(r) : "f"(x));
    return r * 0.6931471805599453f;
}
__device__ __forceinline__ float tanh_f(float x) {
    float e = ex2f(x * 2.8853900817779268f);
    float r; asm("rcp.approx.f32 %0, %1;" : "=f"(r) : "f"(e + 1.0f));
    return fmaf(-2.0f, r, 1.0f);
}
// streaming load (do not pollute L1 — protects L1-resident weights)
__device__ __forceinline__ float4 ldg_na(const float4* p) {
    float4 v;
    asm("ld.global.nc.L1::no_allocate.v4.f32 {%0, %1, %2, %3}, [%4];"
        : "=f"(v.x), "=f"(v.y), "=f"(v.z), "=f"(v.w) : "l"(p));
    return v;
}
// weight load (keep resident in L1)
__device__ __forceinline__ uint4 ldg_el(const uint4* p) {
    uint4 v;
    asm("ld.global.nc.L1::evict_last.v4.u32 {%0, %1, %2, %3}, [%4];"
        : "=r"(v.x), "=r"(v.y), "=r"(v.z), "=r"(v.w) : "l"(p));
    return v;
}

// ---------------------------------------------------------------------------
// dummy x2: aligns ncu's skip-5-capture-1 window onto mlp_kernel
// ---------------------------------------------------------------------------
extern "C" __global__ void dummy_kernel() {}

// ---------------------------------------------------------------------------
// prep: pack weights into k-pair u64 buffers
// ---------------------------------------------------------------------------
extern "C" __global__ void __launch_bounds__(256)
prep_kernel(const float* __restrict__ W1, const float* __restrict__ W2)
{
    int i = blockIdx.x * 256 + threadIdx.x;
    if (i < KP1 * JP) {
        int kp = i / JP, j = i - kp * JP;
        float lo = (j < H) ? W1[(2 * kp) * H + j]     : 0.f;
        float hi = (j < H) ? W1[(2 * kp + 1) * H + j] : 0.f;
        gW1p[i] = pack2(lo, hi);
    } else {
        int i2 = i - KP1 * JP;
        if (i2 < KP2 * T) {
            int kp = i2 >> 6, t = i2 & 63;
            gW2p[i2] = pack2(W2[(2 * kp) * T + t], W2[(2 * kp + 1) * T + t]);
        }
    }
}

// ---------------------------------------------------------------------------
// Kernel A: fused gather + MLP. ROWS=128/block, 1 CTA/SM, square tiles:
// GEMM1 8x8 (208 thr = 16 rg x 13 cg), GEMM2 8x4 (256 thr = 16 rg x 16 tg).
// Activations smem (8-row groups, 80B stride, 1280B per kp); weights L2/L1.
// ---------------------------------------------------------------------------
#define ROWS 128
#define MTHREADS 256
#define OFF_EMB 0
#define OFF_H   81920
#define OFF_SB1 145920
#define OFF_SB2 146336
#define OFF_IDX 146592
#define SMEM_SZ 148128

extern "C" __global__ void __launch_bounds__(MTHREADS, 1)
mlp_kernel(const int* __restrict__ inputs,
           const float* __restrict__ emb_table,
           const float* __restrict__ b1, const float* __restrict__ b2)
{
    extern __shared__ char smem[];
    float* sB1  = (float*)(smem + OFF_SB1);
    float* sB2  = (float*)(smem + OFF_SB2);
    int*   sIdx = (int*)(smem + OFF_IDX);

    const int tid  = threadIdx.x;
    const int row0 = blockIdx.x * ROWS;
    const int b    = row0 >> 9;
    const int s0   = row0 & (S - 1);

    if (tid < JP) sB1[tid] = (tid < H) ? b1[tid] : 0.f;
    if (tid >= 128 && tid < 128 + T) sB2[tid - 128] = b2[tid - 128];
    for (int i = tid; i < ROWS * WW; i += MTHREADS)
        sIdx[i] = inputs[(size_t)row0 * WW + i];
    __syncthreads();

    // gather-sum -> sEmb (k-pair u64, 16 groups x 80B per kp), streaming loads
    for (int i = tid; i < (ROWS * E) / 8; i += MTHREADS) {   // 2048
        int r  = i & (ROWS - 1);
        int e8 = i >> 7;                                     // 0..15
        float a0 = 0.f, a1 = 0.f, a2 = 0.f, a3 = 0.f;
        float a4 = 0.f, a5 = 0.f, a6 = 0.f, a7 = 0.f;
#pragma unroll
        for (int w = 0; w < WW; w++) {
            int idx = sIdx[r * WW + w];
            const float4* p = (const float4*)&emb_table[(size_t)idx * E + e8 * 8];
            float4 v0 = ldg_na(p), v1 = ldg_na(p + 1);
            a0 += v0.x; a1 += v0.y; a2 += v0.z; a3 += v0.w;
            a4 += v1.x; a5 += v1.y; a6 += v1.z; a7 += v1.w;
        }
        char* base = smem + OFF_EMB + (size_t)(e8 * 4) * 1280 + (r >> 3) * 80 + (r & 7) * 8;
        *(u64*)(base)        = pack2(a0, a1);
        *(u64*)(base + 1280) = pack2(a2, a3);
        *(u64*)(base + 2560) = pack2(a4, a5);
        *(u64*)(base + 3840) = pack2(a6, a7);
    }
    if (tid < ROWS) {
        int nz = (sIdx[tid * 3] != 0) + (sIdx[tid * 3 + 1] != 0) + (sIdx[tid * 3 + 2] != 0);
        g_mask[(size_t)(s0 + tid) * B + b] = nz ? 1.f : 0.f;
    }
    __syncthreads();

    // GEMM1: 208 threads, 8 rows x 8 j tiles. tid = cg*16 + rg.
    if (tid < 208) {
        const int rg = tid & 15;             // row group (8 rows)
        const int cg = tid >> 4;             // 0..12
        const int j0 = cg * 8;
        u64 acc[8][8];
#pragma unroll
        for (int jj = 0; jj < 8; jj++) {
            u64 bz = pack2(sB1[j0 + jj], 0.f);
#pragma unroll
            for (int a = 0; a < 8; a++) acc[a][jj] = bz;
        }
        const char* ebase = smem + OFF_EMB + rg * 80;   // 64B contiguous rows
        const u64*  wbase = gW1p + j0;
#pragma unroll 2
        for (int kp = 0; kp < KP1; kp++) {
            uint4 ev[4];
            const uint4* ep = (const uint4*)(ebase + (size_t)kp * 1280);
#pragma unroll
            for (int q = 0; q < 4; q++) ev[q] = ep[q];
            const u64* e = (const u64*)ev;
            uint4 wv[4];
            const uint4* wp = (const uint4*)(wbase + kp * JP);
#pragma unroll
            for (int q = 0; q < 4; q++) wv[q] = ldg_el(wp + q);
            const u64* w = (const u64*)wv;
#pragma unroll
            for (int a = 0; a < 8; a++)
#pragma unroll
                for (int jj = 0; jj < 8; jj++)
                    acc[a][jj] = fma2(e[a], w[jj], acc[a][jj]);
        }
        // tanh + store h (j-pairs) into H region
#pragma unroll
        for (int jp = 0; jp < 4; jp++) {
            int kp2 = cg * 4 + jp;
            if (kp2 < KP2) {
                char* hb = smem + OFF_H + (size_t)kp2 * 1280 + rg * 80;
#pragma unroll
                for (int a = 0; a < 8; a++) {
                    float x0, y0, x1, y1;
                    unpack2(x0, y0, acc[a][jp * 2]);
                    unpack2(x1, y1, acc[a][jp * 2 + 1]);
                    *(u64*)(hb + a * 8) = pack2(tanh_f(x0 + y0), tanh_f(x1 + y1));
                }
            }
        }
    }
    __syncthreads();

    // GEMM2: 256 threads, 8 rows x 4 t tiles. tid = tg*16 + rg.
    {
        const int rg = tid & 15;             // row group (8 rows)
        const int tg = tid >> 4;             // 0..15
        const int t0 = tg * 4;
        u64 acc[8][4];
#pragma unroll
        for (int tt = 0; tt < 4; tt++) {
            u64 bz = pack2(sB2[t0 + tt], 0.f);
#pragma unroll
            for (int a = 0; a < 8; a++) acc[a][tt] = bz;
        }
        const char* hbase = smem + OFF_H + rg * 80;
        const u64*  wbase = gW2p + t0;
#pragma unroll 2
        for (int kp = 0; kp < KP2; kp++) {
            uint4 ev[4];
            const uint4* ep = (const uint4*)(hbase + (size_t)kp * 1280);
#pragma unroll
            for (int q = 0; q < 4; q++) ev[q] = ep[q];
            const u64* e = (const u64*)ev;
            uint4 wv[2];
            const uint4* wp = (const uint4*)(wbase + kp * T);
#pragma unroll
            for (int q = 0; q < 2; q++) wv[q] = ldg_el(wp + q);
            const u64* w = (const u64*)wv;
#pragma unroll
            for (int a = 0; a < 8; a++)
#pragma unroll
                for (int tt = 0; tt < 4; tt++)
                    acc[a][tt] = fma2(e[a], w[tt], acc[a][tt]);
        }
#pragma unroll
        for (int a = 0; a < 8; a++) {
            float o[4];
#pragma unroll
            for (int tt = 0; tt < 4; tt++) {
                float lo, hi; unpack2(lo, hi, acc[a][tt]);
                o[tt] = lo + hi;
            }
            int s = s0 + rg * 8 + a;
            *(float4*)&g_em[((size_t)s * B + b) * T + t0] =
                make_float4(o[0], o[1], o[2], o[3]);
        }
    }
}

// ---------------------------------------------------------------------------
// Kernel C: CRF forward scan + merged numerator — exact R12 fwd body
// (shfl broadcast, register Mexp, renorm/4, prefetch depth 4, unroll 4).
// ---------------------------------------------------------------------------
#define FB 4
#define CTHREADS (FB * 32)

extern "C" __global__ void __launch_bounds__(CTHREADS, 1)
fwd_kernel(const int* __restrict__ tags,
           const float* __restrict__ transitions,
           const float* __restrict__ start_trans,
           const float* __restrict__ end_trans,
           float* __restrict__ out)
{
    const int tid = threadIdx.x;
    const int l   = tid & 31;
    const int b   = blockIdx.x * FB + (tid >> 5);

    // ---- numerator prelude (one warp = one batch) ----
    const int* tb = tags + (size_t)b * S;
    float nm = 0.f;
    {
        float part = 0.f;
        int cnt = 0;
        for (int s = l; s < S; s += 32) {
            float mk = g_mask[(size_t)s * B + b];
            cnt += (mk != 0.f);
            if (s >= 1) {
                int tp = tb[s - 1];
                int tc = tb[s];
                part += (transitions[tp * T + tc] + g_em[((size_t)s * B + b) * T + tc]) * mk;
            }
        }
#pragma unroll
        for (int o = 16; o; o >>= 1) {
            part += __shfl_xor_sync(0xffffffffu, part, o);
            cnt  += __shfl_xor_sync(0xffffffffu, cnt, o);
        }
        if (l == 0) {
            int t0 = tb[0];
            nm = start_trans[t0] + g_em[(size_t)b * T + t0] + part
               + end_trans[tb[cnt - 1]];
        }
    }

    // ---- forward scan ----
    u64 Mp[32][2];
#pragma unroll
    for (int p = 0; p < 32; p++)
#pragma unroll
        for (int c = 0; c < 2; c++) {
            float lo = exp_f(__ldg(&transitions[(2 * p) * T + 2 * l + c]));
            float hi = exp_f(__ldg(&transitions[(2 * p + 1) * T + 2 * l + c]));
            Mp[p][c] = pack2(lo, hi);
        }

    float2 em0 = *(const float2*)&g_em[(size_t)b * T + 2 * l];
    float b0 = exp_f(__ldg(&start_trans[2 * l])     + em0.x);
    float b1 = exp_f(__ldg(&start_trans[2 * l + 1]) + em0.y);
    float C = 0.f;

    float2 emr[4];
    float  mkr[4];
#pragma unroll
    for (int j = 0; j < 4; j++) {
        int ss = 1 + j; if (ss > S - 1) ss = S - 1;
        emr[j] = *(const float2*)&g_em[((size_t)ss * B + b) * T + 2 * l];
        mkr[j] = g_mask[(size_t)ss * B + b];
    }

#pragma unroll 4
    for (int s = 1; s < S; s++) {
        int j = (s - 1) & 3;
        float2 emc = emr[j];
        float  mk  = mkr[j];
        int sn = s + 4; if (sn > S - 1) sn = S - 1;
        emr[j] = *(const float2*)&g_em[((size_t)sn * B + b) * T + 2 * l];
        mkr[j] = g_mask[(size_t)sn * B + b];

        u64 bp = pack2(b0, b1);
        u64 a00 = 0ull, a01 = 0ull, a10 = 0ull, a11 = 0ull;
#pragma unroll
        for (int p = 0; p < 32; p++) {
            u64 bb = __shfl_sync(0xffffffffu, bp, p);
            if (p & 1) { a01 = fma2(bb, Mp[p][0], a01); a11 = fma2(bb, Mp[p][1], a11); }
            else       { a00 = fma2(bb, Mp[p][0], a00); a10 = fma2(bb, Mp[p][1], a10); }
        }
        float x0, y0, x1, y1, x2, y2, x3, y3;
        unpack2(x0, y0, a00); unpack2(x1, y1, a01);
        unpack2(x2, y2, a10); unpack2(x3, y3, a11);
        float n0 = ((x0 + y0) + (x1 + y1)) * exp_f(emc.x);
        float n1 = ((x2 + y2) + (x3 + y3)) * exp_f(emc.y);
        if (mk != 0.f) { b0 = n0; b1 = n1; }

        if ((s & 3) == 0) {
            float mx = fmaxf(b0, b1);
#pragma unroll
            for (int o = 16; o; o >>= 1)
                mx = fmaxf(mx, __shfl_xor_sync(0xffffffffu, mx, o));
            C += log_f(mx);
            float inv = 1.0f / mx;
            b0 *= inv; b1 *= inv;
        }
    }

    float sum = b0 * exp_f(__ldg(&end_trans[2 * l]))
              + b1 * exp_f(__ldg(&end_trans[2 * l + 1]));
#pragma unroll
    for (int o = 16; o; o >>= 1)
        sum += __shfl_xor_sync(0xffffffffu, sum, o);
    if (l == 0)
        out[b] = C + log_f(sum) - nm;
}

// ---------------------------------------------------------------------------
extern "C" void kernel_launch(void* const* d_in, const int* in_sizes, int n_in,
                              void* d_out, int out_size)
{
    const int*   inputs      = (const int*)  d_in[0];
    const int*   tags        = (const int*)  d_in[1];
    const float* emb_table   = (const float*)d_in[2];
    const float* W1          = (const float*)d_in[3];
    const float* b1          = (const float*)d_in[4];
    const float* W2          = (const float*)d_in[5];
    const float* b2          = (const float*)d_in[6];
    const float* start_trans = (const float*)d_in[7];
    const float* end_trans   = (const float*)d_in[8];
    const float* transitions = (const float*)d_in[9];
    float* out = (float*)d_out;

    cudaFuncSetAttribute(mlp_kernel,
                         cudaFuncAttributeMaxDynamicSharedMemorySize, SMEM_SZ);

    dummy_kernel<<<1, 32>>>();
    dummy_kernel<<<1, 32>>>();
    prep_kernel<<<(KP1 * JP + KP2 * T + 255) / 256, 256>>>(W1, W2);
    mlp_kernel<<<(B * S) / ROWS, MTHREADS, SMEM_SZ>>>(inputs, emb_table, b1, b2);
    fwd_kernel<<<B / FB, CTHREADS>>>(tags, transitions, start_trans, end_trans, out);
}

// round 17
// speedup vs baseline: 1.5972x; 1.5972x over previous
#include <cuda_runtime.h>
#include <math.h>
#include <stdint.h>

#define B 512
#define S 512
#define WW 3
#define E 128
#define H 100
#define T 64

// Scratch (static device globals — no runtime allocation)
__device__ float g_em[(size_t)S * B * T];   // em[s][b][t]
__device__ float g_mask[(size_t)S * B];

typedef unsigned long long u64;

#define KP1 64      // k-pairs for GEMM1 (E/2)
#define JP  104     // H padded to 8
#define KP2 50      // k-pairs for GEMM2 (H/2)

__device__ __align__(16) u64 gW1p[KP1 * JP];   // (W1[2kp][j], W1[2kp+1][j])
__device__ __align__(16) u64 gW2p[KP2 * T];    // (W2[2kp][t], W2[2kp+1][t])

// ---- helpers ---------------------------------------------------------------
__device__ __forceinline__ u64 pack2(float lo, float hi) {
    u64 d; asm("mov.b64 %0, {%1, %2};" : "=l"(d) : "f"(lo), "f"(hi)); return d;
}
__device__ __forceinline__ void unpack2(float& lo, float& hi, u64 v) {
    asm("mov.b64 {%0, %1}, %2;" : "=f"(lo), "=f"(hi) : "l"(v));
}
__device__ __forceinline__ u64 fma2(u64 a, u64 b2, u64 c) {
    u64 d; asm("fma.rn.f32x2 %0, %1, %2, %3;" : "=l"(d) : "l"(a), "l"(b2), "l"(c));
    return d;
}
__device__ __forceinline__ float ex2f(float x) {
    float r; asm("ex2.approx.f32 %0, %1;" : "=f"(r) : "f"(x)); return r;
}
__device__ __forceinline__ float exp_f(float x) { return ex2f(x * 1.4426950408889634f); }
__device__ __forceinline__ float log_f(float x) {
    float r; asm("lg2.approx.f32 %0, %1;" : "=f"(r) : "f"(x));
    return r * 0.6931471805599453f;
}
__device__ __forceinline__ float tanh_f(float x) {
    float e = ex2f(x * 2.8853900817779268f);
    float r; asm("rcp.approx.f32 %0, %1;" : "=f"(r) : "f"(e + 1.0f));
    return fmaf(-2.0f, r, 1.0f);
}
// streaming load (do not pollute L1 — protects L1-resident weights)
__device__ __forceinline__ float4 ldg_na(const float4* p) {
    float4 v;
    asm("ld.global.nc.L1::no_allocate.v4.f32 {%0, %1, %2, %3}, [%4];"
        : "=f"(v.x), "=f"(v.y), "=f"(v.z), "=f"(v.w) : "l"(p));
    return v;
}
// weight load (keep resident in L1)
__device__ __forceinline__ uint4 ldg_el(const uint4* p) {
    uint4 v;
    asm("ld.global.nc.L1::evict_last.v4.u32 {%0, %1, %2, %3}, [%4];"
        : "=r"(v.x), "=r"(v.y), "=r"(v.z), "=r"(v.w) : "l"(p));
    return v;
}

// ---------------------------------------------------------------------------
// dummy x2: aligns ncu's skip-5-capture-1 window onto mlp_kernel
// ---------------------------------------------------------------------------
extern "C" __global__ void dummy_kernel() {}

// ---------------------------------------------------------------------------
// prep: pack weights into k-pair u64 buffers
// ---------------------------------------------------------------------------
extern "C" __global__ void __launch_bounds__(256)
prep_kernel(const float* __restrict__ W1, const float* __restrict__ W2)
{
    int i = blockIdx.x * 256 + threadIdx.x;
    if (i < KP1 * JP) {
        int kp = i / JP, j = i - kp * JP;
        float lo = (j < H) ? W1[(2 * kp) * H + j]     : 0.f;
        float hi = (j < H) ? W1[(2 * kp + 1) * H + j] : 0.f;
        gW1p[i] = pack2(lo, hi);
    } else {
        int i2 = i - KP1 * JP;
        if (i2 < KP2 * T) {
            int kp = i2 >> 6, t = i2 & 63;
            gW2p[i2] = pack2(W2[(2 * kp) * T + t], W2[(2 * kp + 1) * T + t]);
        }
    }
}

// ---------------------------------------------------------------------------
// Kernel A: fused gather + MLP. ROWS=64, 128 threads/block, 2 CTA/SM:
// R14's square tiles (good L1 profile) at 2.5x the warp supply.
// GEMM1 8x8 (104 thr = 8 rg x 13 cg), GEMM2 8x4 (128 thr = 8 rg x 16 tg).
// ---------------------------------------------------------------------------
#define ROWS 64
#define MTHREADS 128
#define OFF_EMB 0
#define OFF_H   40960
#define OFF_SB1 72960
#define OFF_SB2 73376
#define OFF_IDX 73632
#define SMEM_SZ 74400

extern "C" __global__ void __launch_bounds__(MTHREADS, 2)
mlp_kernel(const int* __restrict__ inputs,
           const float* __restrict__ emb_table,
           const float* __restrict__ b1, const float* __restrict__ b2)
{
    extern __shared__ char smem[];
    float* sB1  = (float*)(smem + OFF_SB1);
    float* sB2  = (float*)(smem + OFF_SB2);
    int*   sIdx = (int*)(smem + OFF_IDX);

    const int tid  = threadIdx.x;
    const int row0 = blockIdx.x * ROWS;
    const int b    = row0 >> 9;
    const int s0   = row0 & (S - 1);

    if (tid < JP) sB1[tid] = (tid < H) ? b1[tid] : 0.f;
    if (tid < T) sB2[tid] = b2[tid];
    for (int i = tid; i < ROWS * WW; i += MTHREADS)
        sIdx[i] = inputs[(size_t)row0 * WW + i];
    __syncthreads();

    // gather-sum -> sEmb (k-pair u64, 8 groups x 80B per kp), streaming loads
    for (int i = tid; i < (ROWS * E) / 8; i += MTHREADS) {   // 1024
        int r  = i & (ROWS - 1);
        int e8 = i >> 6;                                     // 0..15
        float a0 = 0.f, a1 = 0.f, a2 = 0.f, a3 = 0.f;
        float a4 = 0.f, a5 = 0.f, a6 = 0.f, a7 = 0.f;
#pragma unroll
        for (int w = 0; w < WW; w++) {
            int idx = sIdx[r * WW + w];
            const float4* p = (const float4*)&emb_table[(size_t)idx * E + e8 * 8];
            float4 v0 = ldg_na(p), v1 = ldg_na(p + 1);
            a0 += v0.x; a1 += v0.y; a2 += v0.z; a3 += v0.w;
            a4 += v1.x; a5 += v1.y; a6 += v1.z; a7 += v1.w;
        }
        char* base = smem + OFF_EMB + (size_t)(e8 * 4) * 640 + (r >> 3) * 80 + (r & 7) * 8;
        *(u64*)(base)        = pack2(a0, a1);
        *(u64*)(base + 640)  = pack2(a2, a3);
        *(u64*)(base + 1280) = pack2(a4, a5);
        *(u64*)(base + 1920) = pack2(a6, a7);
    }
    if (tid < ROWS) {
        int nz = (sIdx[tid * 3] != 0) + (sIdx[tid * 3 + 1] != 0) + (sIdx[tid * 3 + 2] != 0);
        g_mask[(size_t)(s0 + tid) * B + b] = nz ? 1.f : 0.f;
    }
    __syncthreads();

    // GEMM1: 104 threads, 8 rows x 8 j tiles. tid = cg*8 + rg.
    if (tid < 104) {
        const int rg = tid & 7;              // row group (8 rows)
        const int cg = tid >> 3;             // 0..12
        const int j0 = cg * 8;
        u64 acc[8][8];
#pragma unroll
        for (int jj = 0; jj < 8; jj++) {
            u64 bz = pack2(sB1[j0 + jj], 0.f);
#pragma unroll
            for (int a = 0; a < 8; a++) acc[a][jj] = bz;
        }
        const char* ebase = smem + OFF_EMB + rg * 80;   // 64B contiguous rows
        const u64*  wbase = gW1p + j0;
#pragma unroll 2
        for (int kp = 0; kp < KP1; kp++) {
            uint4 ev[4];
            const uint4* ep = (const uint4*)(ebase + (size_t)kp * 640);
#pragma unroll
            for (int q = 0; q < 4; q++) ev[q] = ep[q];
            const u64* e = (const u64*)ev;
            uint4 wv[4];
            const uint4* wp = (const uint4*)(wbase + kp * JP);
#pragma unroll
            for (int q = 0; q < 4; q++) wv[q] = ldg_el(wp + q);
            const u64* w = (const u64*)wv;
#pragma unroll
            for (int a = 0; a < 8; a++)
#pragma unroll
                for (int jj = 0; jj < 8; jj++)
                    acc[a][jj] = fma2(e[a], w[jj], acc[a][jj]);
        }
        // tanh + store h (j-pairs) into H region
#pragma unroll
        for (int jp = 0; jp < 4; jp++) {
            int kp2 = cg * 4 + jp;
            if (kp2 < KP2) {
                char* hb = smem + OFF_H + (size_t)kp2 * 640 + rg * 80;
#pragma unroll
                for (int a = 0; a < 8; a++) {
                    float x0, y0, x1, y1;
                    unpack2(x0, y0, acc[a][jp * 2]);
                    unpack2(x1, y1, acc[a][jp * 2 + 1]);
                    *(u64*)(hb + a * 8) = pack2(tanh_f(x0 + y0), tanh_f(x1 + y1));
                }
            }
        }
    }
    __syncthreads();

    // GEMM2: 128 threads, 8 rows x 4 t tiles. tid = tg*8 + rg.
    {
        const int rg = tid & 7;              // row group (8 rows)
        const int tg = tid >> 3;             // 0..15
        const int t0 = tg * 4;
        u64 acc[8][4];
#pragma unroll
        for (int tt = 0; tt < 4; tt++) {
            u64 bz = pack2(sB2[t0 + tt], 0.f);
#pragma unroll
            for (int a = 0; a < 8; a++) acc[a][tt] = bz;
        }
        const char* hbase = smem + OFF_H + rg * 80;
        const u64*  wbase = gW2p + t0;
#pragma unroll 2
        for (int kp = 0; kp < KP2; kp++) {
            uint4 ev[4];
            const uint4* ep = (const uint4*)(hbase + (size_t)kp * 640);
#pragma unroll
            for (int q = 0; q < 4; q++) ev[q] = ep[q];
            const u64* e = (const u64*)ev;
            uint4 wv[2];
            const uint4* wp = (const uint4*)(wbase + kp * T);
#pragma unroll
            for (int q = 0; q < 2; q++) wv[q] = ldg_el(wp + q);
            const u64* w = (const u64*)wv;
#pragma unroll
            for (int a = 0; a < 8; a++)
#pragma unroll
                for (int tt = 0; tt < 4; tt++)
                    acc[a][tt] = fma2(e[a], w[tt], acc[a][tt]);
        }
#pragma unroll
        for (int a = 0; a < 8; a++) {
            float o[4];
#pragma unroll
            for (int tt = 0; tt < 4; tt++) {
                float lo, hi; unpack2(lo, hi, acc[a][tt]);
                o[tt] = lo + hi;
            }
            int s = s0 + rg * 8 + a;
            *(float4*)&g_em[((size_t)s * B + b) * T + t0] =
                make_float4(o[0], o[1], o[2], o[3]);
        }
    }
}

// ---------------------------------------------------------------------------
// Kernel C: CRF forward scan + merged numerator — exact R12 fwd body
// (shfl broadcast, register Mexp, renorm/4, prefetch depth 4, unroll 4).
// ---------------------------------------------------------------------------
#define FB 4
#define CTHREADS (FB * 32)

extern "C" __global__ void __launch_bounds__(CTHREADS, 1)
fwd_kernel(const int* __restrict__ tags,
           const float* __restrict__ transitions,
           const float* __restrict__ start_trans,
           const float* __restrict__ end_trans,
           float* __restrict__ out)
{
    const int tid = threadIdx.x;
    const int l   = tid & 31;
    const int b   = blockIdx.x * FB + (tid >> 5);

    // ---- numerator prelude (one warp = one batch) ----
    const int* tb = tags + (size_t)b * S;
    float nm = 0.f;
    {
        float part = 0.f;
        int cnt = 0;
        for (int s = l; s < S; s += 32) {
            float mk = g_mask[(size_t)s * B + b];
            cnt += (mk != 0.f);
            if (s >= 1) {
                int tp = tb[s - 1];
                int tc = tb[s];
                part += (transitions[tp * T + tc] + g_em[((size_t)s * B + b) * T + tc]) * mk;
            }
        }
#pragma unroll
        for (int o = 16; o; o >>= 1) {
            part += __shfl_xor_sync(0xffffffffu, part, o);
            cnt  += __shfl_xor_sync(0xffffffffu, cnt, o);
        }
        if (l == 0) {
            int t0 = tb[0];
            nm = start_trans[t0] + g_em[(size_t)b * T + t0] + part
               + end_trans[tb[cnt - 1]];
        }
    }

    // ---- forward scan ----
    u64 Mp[32][2];
#pragma unroll
    for (int p = 0; p < 32; p++)
#pragma unroll
        for (int c = 0; c < 2; c++) {
            float lo = exp_f(__ldg(&transitions[(2 * p) * T + 2 * l + c]));
            float hi = exp_f(__ldg(&transitions[(2 * p + 1) * T + 2 * l + c]));
            Mp[p][c] = pack2(lo, hi);
        }

    float2 em0 = *(const float2*)&g_em[(size_t)b * T + 2 * l];
    float b0 = exp_f(__ldg(&start_trans[2 * l])     + em0.x);
    float b1 = exp_f(__ldg(&start_trans[2 * l + 1]) + em0.y);
    float C = 0.f;

    float2 emr[4];
    float  mkr[4];
#pragma unroll
    for (int j = 0; j < 4; j++) {
        int ss = 1 + j; if (ss > S - 1) ss = S - 1;
        emr[j] = *(const float2*)&g_em[((size_t)ss * B + b) * T + 2 * l];
        mkr[j] = g_mask[(size_t)ss * B + b];
    }

#pragma unroll 4
    for (int s = 1; s < S; s++) {
        int j = (s - 1) & 3;
        float2 emc = emr[j];
        float  mk  = mkr[j];
        int sn = s + 4; if (sn > S - 1) sn = S - 1;
        emr[j] = *(const float2*)&g_em[((size_t)sn * B + b) * T + 2 * l];
        mkr[j] = g_mask[(size_t)sn * B + b];

        u64 bp = pack2(b0, b1);
        u64 a00 = 0ull, a01 = 0ull, a10 = 0ull, a11 = 0ull;
#pragma unroll
        for (int p = 0; p < 32; p++) {
            u64 bb = __shfl_sync(0xffffffffu, bp, p);
            if (p & 1) { a01 = fma2(bb, Mp[p][0], a01); a11 = fma2(bb, Mp[p][1], a11); }
            else       { a00 = fma2(bb, Mp[p][0], a00); a10 = fma2(bb, Mp[p][1], a10); }
        }
        float x0, y0, x1, y1, x2, y2, x3, y3;
        unpack2(x0, y0, a00); unpack2(x1, y1, a01);
        unpack2(x2, y2, a10); unpack2(x3, y3, a11);
        float n0 = ((x0 + y0) + (x1 + y1)) * exp_f(emc.x);
        float n1 = ((x2 + y2) + (x3 + y3)) * exp_f(emc.y);
        if (mk != 0.f) { b0 = n0; b1 = n1; }

        if ((s & 3) == 0) {
            float mx = fmaxf(b0, b1);
#pragma unroll
            for (int o = 16; o; o >>= 1)
                mx = fmaxf(mx, __shfl_xor_sync(0xffffffffu, mx, o));
            C += log_f(mx);
            float inv = 1.0f / mx;
            b0 *= inv; b1 *= inv;
        }
    }

    float sum = b0 * exp_f(__ldg(&end_trans[2 * l]))
              + b1 * exp_f(__ldg(&end_trans[2 * l + 1]));
#pragma unroll
    for (int o = 16; o; o >>= 1)
        sum += __shfl_xor_sync(0xffffffffu, sum, o);
    if (l == 0)
        out[b] = C + log_f(sum) - nm;
}

// ---------------------------------------------------------------------------
extern "C" void kernel_launch(void* const* d_in, const int* in_sizes, int n_in,
                              void* d_out, int out_size)
{
    const int*   inputs      = (const int*)  d_in[0];
    const int*   tags        = (const int*)  d_in[1];
    const float* emb_table   = (const float*)d_in[2];
    const float* W1          = (const float*)d_in[3];
    const float* b1          = (const float*)d_in[4];
    const float* W2          = (const float*)d_in[5];
    const float* b2          = (const float*)d_in[6];
    const float* start_trans = (const float*)d_in[7];
    const float* end_trans   = (const float*)d_in[8];
    const float* transitions = (const float*)d_in[9];
    float* out = (float*)d_out;

    cudaFuncSetAttribute(mlp_kernel,
                         cudaFuncAttributeMaxDynamicSharedMemorySize, SMEM_SZ);

    dummy_kernel<<<1, 32>>>();
    dummy_kernel<<<1, 32>>>();
    prep_kernel<<<(KP1 * JP + KP2 * T + 255) / 256, 256>>>(W1, W2);
    mlp_kernel<<<(B * S) / ROWS, MTHREADS, SMEM_SZ>>>(inputs, emb_table, b1, b2);
    fwd_kernel<<<B / FB, CTHREADS>>>(tags, transitions, start_trans, end_trans, out);
}